// round 1
// baseline (speedup 1.0000x reference)
#include <cuda_runtime.h>
#include <math.h>

// Problem dims
#define VV 20000
#define EE 256
#define HH 512
#define BB 128
#define SS 64
#define TD 32

// ---------------- scratch (device globals; no allocation) ----------------
__device__ float g_xg[BB * SS * 2048];        // encoder input-gates  [b][s][4H]
__device__ float g_enc_out[BB * SS * HH];     // encoder hiddens      [b][s][H]
__device__ float g_keys[BB * SS * HH];        // keys_proj            [b][s][H]
__device__ float g_embW[TD * BB * 2048];      // dec emb@Wih[:, :E].T + dec_b  [t][b][4H]
__device__ float g_hs[TD * BB * HH];          // decoder hidden states [t][b][H]
__device__ float g_h0[BB * HH];
__device__ float g_h1[BB * HH];
__device__ float g_c[BB * HH];
__device__ float g_q[BB * HH];
__device__ float g_ctx[BB * HH];
__device__ int   g_rows[TD * BB];

__device__ __forceinline__ float sigf(float x) { return 1.f / (1.f + __expf(-x)); }

// ---------------- generic SGEMM-NT: C[m,n] = sum_k A[ar(m),k]*B[n,k] + bias[n] ----------------
// 128x128 tile, BK=8, 256 threads, 8x8 per thread.
// mode 0: C row-major [M,N].  mode 1: logits remap m=t*128+b -> row b*TD+t.
__global__ __launch_bounds__(256) void gemm_nt(
    const float* __restrict__ A, int lda, const int* __restrict__ arow,
    const float* __restrict__ B, int ldb, const float* __restrict__ bias,
    float* __restrict__ C, int M, int N, int K, int mode)
{
    __shared__ float As[8][132];
    __shared__ float Bs[8][132];
    const int bn = blockIdx.x * 128;
    const int bm = blockIdx.y * 128;
    const int tid = threadIdx.x;
    const int lr = tid >> 1;          // 0..127
    const int lk = (tid & 1) << 2;    // 0 or 4
    const int tm = (tid >> 4) << 3;
    const int tn = (tid & 15) << 3;

    const int am = bm + lr;           // all M are multiples of 128 here
    const int ar = arow ? arow[am] : am;
    const float* Ap = A + (size_t)ar * lda + lk;
    const int bnr = bn + lr;
    const bool bval = (bnr < N);
    const float* Bp = B + (size_t)(bval ? bnr : 0) * ldb + lk;

    float acc[8][8];
#pragma unroll
    for (int i = 0; i < 8; i++)
#pragma unroll
        for (int j = 0; j < 8; j++) acc[i][j] = 0.f;

    for (int k0 = 0; k0 < K; k0 += 8) {
        float4 av = *(const float4*)(Ap + k0);
        float4 bv = bval ? *(const float4*)(Bp + k0) : make_float4(0.f, 0.f, 0.f, 0.f);
        __syncthreads();
        As[lk + 0][lr] = av.x; As[lk + 1][lr] = av.y; As[lk + 2][lr] = av.z; As[lk + 3][lr] = av.w;
        Bs[lk + 0][lr] = bv.x; Bs[lk + 1][lr] = bv.y; Bs[lk + 2][lr] = bv.z; Bs[lk + 3][lr] = bv.w;
        __syncthreads();
#pragma unroll
        for (int kk = 0; kk < 8; kk++) {
            float a[8], b[8];
            *(float4*)(a)     = *(const float4*)&As[kk][tm];
            *(float4*)(a + 4) = *(const float4*)&As[kk][tm + 4];
            *(float4*)(b)     = *(const float4*)&Bs[kk][tn];
            *(float4*)(b + 4) = *(const float4*)&Bs[kk][tn + 4];
#pragma unroll
            for (int i = 0; i < 8; i++)
#pragma unroll
                for (int j = 0; j < 8; j++)
                    acc[i][j] += a[i] * b[j];
        }
    }
#pragma unroll
    for (int i = 0; i < 8; i++) {
        const int m = bm + tm + i;
#pragma unroll
        for (int j = 0; j < 8; j++) {
            const int n = bn + tn + j;
            if (n < N) {
                float v = acc[i][j] + (bias ? bias[n] : 0.f);
                size_t off;
                if (mode == 1) off = (size_t)((m & 127) * TD + (m >> 7)) * N + n;
                else           off = (size_t)m * N + n;
                C[off] = v;
            }
        }
    }
}

// ---------------- encoder step: gates = xg[:,t,:] + h@Whh.T, fused LSTM cell ----------------
// tile 32j x 32b, thread = 2j x 2b, 4 gates. grid (16,4), 256 threads.
__global__ __launch_bounds__(256) void enc_step(const float* __restrict__ Whh, int t)
{
    __shared__ float hs[32][34];       // [kk][b]
    __shared__ float ws[4][32][34];    // [g][kk][jj]
    const int tid = threadIdx.x;
    const int tj = tid & 15;
    const int tb = tid >> 4;
    const int j0 = blockIdx.x * 32;
    const int b0 = blockIdx.y * 32;
    const float* hin = (t & 1) ? g_h1 : g_h0;
    float* hout      = (t & 1) ? g_h0 : g_h1;

    float acc[4][2][2];
#pragma unroll
    for (int g = 0; g < 4; g++) { acc[g][0][0] = acc[g][0][1] = acc[g][1][0] = acc[g][1][1] = 0.f; }

    for (int k0 = 0; k0 < 512; k0 += 32) {
        __syncthreads();
#pragma unroll
        for (int i = 0; i < 4; i++) {
            int idx = i * 256 + tid;
            int bb = idx >> 5, kk = idx & 31;
            hs[kk][bb] = hin[(size_t)(b0 + bb) * 512 + k0 + kk];
        }
#pragma unroll
        for (int i = 0; i < 16; i++) {
            int idx = i * 256 + tid;
            int g = idx >> 10, jj = (idx >> 5) & 31, kk = idx & 31;
            ws[g][kk][jj] = Whh[(size_t)((g << 9) + j0 + jj) * 512 + k0 + kk];
        }
        __syncthreads();
#pragma unroll
        for (int kk = 0; kk < 32; kk++) {
            float2 hp = *(const float2*)&hs[kk][tb * 2];
#pragma unroll
            for (int g = 0; g < 4; g++) {
                float2 wp = *(const float2*)&ws[g][kk][tj * 2];
                acc[g][0][0] += hp.x * wp.x;
                acc[g][0][1] += hp.x * wp.y;
                acc[g][1][0] += hp.y * wp.x;
                acc[g][1][1] += hp.y * wp.y;
            }
        }
    }
#pragma unroll
    for (int bi = 0; bi < 2; bi++)
#pragma unroll
        for (int ji = 0; ji < 2; ji++) {
            const int b = b0 + tb * 2 + bi;
            const int j = j0 + tj * 2 + ji;
            const size_t xb = ((size_t)b * SS + t) * 2048 + j;
            float ig = acc[0][bi][ji] + g_xg[xb];
            float fg = acc[1][bi][ji] + g_xg[xb + 512];
            float gg = acc[2][bi][ji] + g_xg[xb + 1024];
            float og = acc[3][bi][ji] + g_xg[xb + 1536];
            float cp = g_c[b * 512 + j];
            float cn = sigf(fg) * cp + sigf(ig) * tanhf(gg);
            float hn = sigf(og) * tanhf(cn);
            g_c[b * 512 + j] = cn;
            hout[b * 512 + j] = hn;
            g_enc_out[((size_t)b * SS + t) * 512 + j] = hn;
        }
}

// ---------------- decoder step: gates = embW[t] + [ctx,h]@W.T, fused cell ----------------
__global__ __launch_bounds__(256) void dec_step(const float* __restrict__ dWih,
                                                const float* __restrict__ dWhh, int t)
{
    __shared__ float hs[32][34];
    __shared__ float ws[4][32][34];
    const int tid = threadIdx.x;
    const int tj = tid & 15;
    const int tb = tid >> 4;
    const int j0 = blockIdx.x * 32;
    const int b0 = blockIdx.y * 32;
    const float* hin = (t & 1) ? g_h1 : g_h0;
    float* hout      = (t & 1) ? g_h0 : g_h1;

    float acc[4][2][2];
#pragma unroll
    for (int g = 0; g < 4; g++) { acc[g][0][0] = acc[g][0][1] = acc[g][1][0] = acc[g][1][1] = 0.f; }

    for (int k0 = 0; k0 < 1024; k0 += 32) {
        const bool isCtx = (k0 < 512);
        __syncthreads();
#pragma unroll
        for (int i = 0; i < 4; i++) {
            int idx = i * 256 + tid;
            int bb = idx >> 5, kk = idx & 31;
            int kg = k0 + kk;
            hs[kk][bb] = isCtx ? g_ctx[(size_t)(b0 + bb) * 512 + kg]
                               : hin[(size_t)(b0 + bb) * 512 + kg - 512];
        }
#pragma unroll
        for (int i = 0; i < 16; i++) {
            int idx = i * 256 + tid;
            int g = idx >> 10, jj = (idx >> 5) & 31, kk = idx & 31;
            int kg = k0 + kk;
            int n = (g << 9) + j0 + jj;
            ws[g][kk][jj] = isCtx ? dWih[(size_t)n * 768 + 256 + kg]
                                  : dWhh[(size_t)n * 512 + kg - 512];
        }
        __syncthreads();
#pragma unroll
        for (int kk = 0; kk < 32; kk++) {
            float2 hp = *(const float2*)&hs[kk][tb * 2];
#pragma unroll
            for (int g = 0; g < 4; g++) {
                float2 wp = *(const float2*)&ws[g][kk][tj * 2];
                acc[g][0][0] += hp.x * wp.x;
                acc[g][0][1] += hp.x * wp.y;
                acc[g][1][0] += hp.y * wp.x;
                acc[g][1][1] += hp.y * wp.y;
            }
        }
    }
#pragma unroll
    for (int bi = 0; bi < 2; bi++)
#pragma unroll
        for (int ji = 0; ji < 2; ji++) {
            const int b = b0 + tb * 2 + bi;
            const int j = j0 + tj * 2 + ji;
            const size_t mb = ((size_t)t * BB + b) * 2048 + j;
            float ig = acc[0][bi][ji] + g_embW[mb];
            float fg = acc[1][bi][ji] + g_embW[mb + 512];
            float gg = acc[2][bi][ji] + g_embW[mb + 1024];
            float og = acc[3][bi][ji] + g_embW[mb + 1536];
            float cp = g_c[b * 512 + j];
            float cn = sigf(fg) * cp + sigf(ig) * tanhf(gg);
            float hn = sigf(og) * tanhf(cn);
            g_c[b * 512 + j] = cn;
            hout[b * 512 + j] = hn;
            g_hs[((size_t)t * BB + b) * 512 + j] = hn;
        }
}

// ---------------- q = h@Wq.T + bq (per decoder step) ----------------
__global__ __launch_bounds__(256) void q_step(const float* __restrict__ Wq,
                                              const float* __restrict__ bq, int t)
{
    __shared__ float hs[32][34];
    __shared__ float ws[32][34];
    const int tid = threadIdx.x;
    const int tj = tid & 15;
    const int tb = tid >> 4;
    const int j0 = blockIdx.x * 32;
    const int b0 = blockIdx.y * 32;
    const float* hin = (t & 1) ? g_h1 : g_h0;

    float acc[2][2] = {{0.f, 0.f}, {0.f, 0.f}};
    for (int k0 = 0; k0 < 512; k0 += 32) {
        __syncthreads();
#pragma unroll
        for (int i = 0; i < 4; i++) {
            int idx = i * 256 + tid;
            int bb = idx >> 5, kk = idx & 31;
            hs[kk][bb] = hin[(size_t)(b0 + bb) * 512 + k0 + kk];
        }
#pragma unroll
        for (int i = 0; i < 4; i++) {
            int idx = i * 256 + tid;
            int jj = idx >> 5, kk = idx & 31;
            ws[kk][jj] = Wq[(size_t)(j0 + jj) * 512 + k0 + kk];
        }
        __syncthreads();
#pragma unroll
        for (int kk = 0; kk < 32; kk++) {
            float2 hp = *(const float2*)&hs[kk][tb * 2];
            float2 wp = *(const float2*)&ws[kk][tj * 2];
            acc[0][0] += hp.x * wp.x;
            acc[0][1] += hp.x * wp.y;
            acc[1][0] += hp.y * wp.x;
            acc[1][1] += hp.y * wp.y;
        }
    }
#pragma unroll
    for (int bi = 0; bi < 2; bi++)
#pragma unroll
        for (int ji = 0; ji < 2; ji++) {
            const int b = b0 + tb * 2 + bi;
            const int j = j0 + tj * 2 + ji;
            g_q[b * 512 + j] = acc[bi][ji] + bq[j];
        }
}

// ---------------- attention: scores/softmax/context (block per batch element) ----------------
__global__ __launch_bounds__(256) void att_step(const float* __restrict__ v_w,
                                                const float* __restrict__ v_b,
                                                const int* __restrict__ src,
                                                float* __restrict__ attn_out,
                                                int t, int writeAttn)
{
    const int b = blockIdx.x;
    const int tid = threadIdx.x;
    __shared__ float qs[512], vs[512], sc[64];
    qs[tid] = g_q[b * 512 + tid];
    qs[tid + 256] = g_q[b * 512 + tid + 256];
    vs[tid] = v_w[tid];
    vs[tid + 256] = v_w[tid + 256];
    __syncthreads();
    const int warp = tid >> 5, lane = tid & 31;
    for (int s = warp; s < 64; s += 8) {
        const float* kp = g_keys + ((size_t)b * SS + s) * 512;
        float sum = 0.f;
        for (int j = lane; j < 512; j += 32)
            sum += tanhf(qs[j] + kp[j]) * vs[j];
#pragma unroll
        for (int o = 16; o; o >>= 1) sum += __shfl_xor_sync(0xffffffffu, sum, o);
        if (lane == 0) {
            sum += v_b[0];
            if (src[b * SS + s] == 0) sum = -1e9f;
            sc[s] = sum;
        }
    }
    __syncthreads();
    if (warp == 0) {
        float a0 = sc[lane], a1 = sc[lane + 32];
        float m = fmaxf(a0, a1);
#pragma unroll
        for (int o = 16; o; o >>= 1) m = fmaxf(m, __shfl_xor_sync(0xffffffffu, m, o));
        float e0 = __expf(a0 - m), e1 = __expf(a1 - m);
        float ss = e0 + e1;
#pragma unroll
        for (int o = 16; o; o >>= 1) ss += __shfl_xor_sync(0xffffffffu, ss, o);
        float inv = 1.f / ss;
        sc[lane] = e0 * inv;
        sc[lane + 32] = e1 * inv;
        if (writeAttn) {
            attn_out[((size_t)b * TD + t) * SS + lane] = e0 * inv;
            attn_out[((size_t)b * TD + t) * SS + lane + 32] = e1 * inv;
        }
    }
    __syncthreads();
    for (int j = tid; j < 512; j += 256) {
        float a = 0.f;
        const float* ep = g_enc_out + (size_t)b * SS * 512 + j;
#pragma unroll 8
        for (int s = 0; s < 64; s++) a += sc[s] * ep[(size_t)s * 512];
        g_ctx[b * 512 + j] = a;
    }
}

// ---------------- small helpers ----------------
__global__ void zero_hc()
{
    int i = blockIdx.x * 256 + threadIdx.x;   // grid 256 -> 65536
    g_h0[i] = 0.f;
    g_c[i] = 0.f;
}

__global__ void build_rows(const int* __restrict__ tgt)
{
    int i = blockIdx.x * 256 + threadIdx.x;   // grid 16 -> 4096
    if (i < TD * BB) {
        int tt = i >> 7, b = i & 127;
        g_rows[i] = (tt == 0) ? 1 : tgt[b * 33 + tt];
    }
}

// ---------------- launch ----------------
extern "C" void kernel_launch(void* const* d_in, const int* in_sizes, int n_in,
                              void* d_out, int out_size)
{
    (void)in_sizes; (void)n_in;
    const int*   src     = (const int*)d_in[0];
    const int*   tgt     = (const int*)d_in[1];
    const float* enc_emb = (const float*)d_in[2];
    const float* enc_Wih = (const float*)d_in[3];
    const float* enc_Whh = (const float*)d_in[4];
    const float* enc_b   = (const float*)d_in[5];
    const float* dec_emb = (const float*)d_in[6];
    const float* Wq      = (const float*)d_in[7];
    const float* bq      = (const float*)d_in[8];
    const float* Wk      = (const float*)d_in[9];
    const float* bk      = (const float*)d_in[10];
    const float* v_w     = (const float*)d_in[11];
    const float* v_b     = (const float*)d_in[12];
    const float* dWih    = (const float*)d_in[13];
    const float* dWhh    = (const float*)d_in[14];
    const float* db      = (const float*)d_in[15];
    const float* Wo      = (const float*)d_in[16];
    const float* bo      = (const float*)d_in[17];
    float* out = (float*)d_out;

    void *p_xg, *p_enc, *p_keys, *p_embW, *p_hs, *p_rows;
    cudaGetSymbolAddress(&p_xg,   g_xg);
    cudaGetSymbolAddress(&p_enc,  g_enc_out);
    cudaGetSymbolAddress(&p_keys, g_keys);
    cudaGetSymbolAddress(&p_embW, g_embW);
    cudaGetSymbolAddress(&p_hs,   g_hs);
    cudaGetSymbolAddress(&p_rows, g_rows);

    // init h0=0, c0=0
    zero_hc<<<256, 256>>>();

    // encoder input gates: [8192,2048] = emb[src] @ enc_Wih.T + enc_b
    gemm_nt<<<dim3(16, 64), 256>>>(enc_emb, 256, src, enc_Wih, 256, enc_b,
                                   (float*)p_xg, 8192, 2048, 256, 0);

    // encoder recurrence
    for (int t = 0; t < SS; t++)
        enc_step<<<dim3(16, 4), 256>>>(enc_Whh, t);
    // final (h,c) now in g_h0 / g_c

    // keys_proj = enc_out @ Wk.T + bk
    gemm_nt<<<dim3(4, 64), 256>>>((const float*)p_enc, 512, nullptr, Wk, 512, bk,
                                  (float*)p_keys, 8192, 512, 512, 0);

    // decoder embedding rows + precomputed emb@Wih[:, :E].T + dec_b
    build_rows<<<16, 256>>>(tgt);
    gemm_nt<<<dim3(16, 32), 256>>>(dec_emb, 256, (const int*)p_rows, dWih, 768, db,
                                   (float*)p_embW, 4096, 2048, 256, 0);

    const long long LOGITS = (long long)BB * TD * VV;           // 81,920,000
    const long long TOTAL  = LOGITS + (long long)BB * TD * SS;  // +262,144
    int writeAttn = ((long long)out_size >= TOTAL);
    float* attn = out + LOGITS;

    // decoder recurrence
    for (int t = 0; t < TD; t++) {
        q_step<<<dim3(16, 4), 256>>>(Wq, bq, t);
        att_step<<<128, 256>>>(v_w, v_b, src, attn, t, writeAttn);
        dec_step<<<dim3(16, 4), 256>>>(dWih, dWhh, t);
    }

    // logits = hs @ Wo.T + bo  (one batched GEMM over all 32 steps)
    gemm_nt<<<dim3(157, 32), 256>>>((const float*)p_hs, 512, nullptr, Wo, 512, bo,
                                    out, 4096, 20000, 512, 1);
}